// round 6
// baseline (speedup 1.0000x reference)
#include <cuda_runtime.h>
#include <cuda_fp16.h>
#include <cstdint>

// ============================ problem dims ============================
#define M_TOTAL 8192   // 4 * 2048 tokens
#define K_DIM   2048
#define H_DIM   8192

// ============================ scratch (device globals; no allocs) ============================
__device__ __align__(128) __half g_xh [(size_t)M_TOTAL * K_DIM];   // x  -> fp16
__device__ __align__(128) __half g_wgh[(size_t)H_DIM   * K_DIM];   // w_gate -> fp16
__device__ __align__(128) __half g_wuh[(size_t)H_DIM   * K_DIM];   // w_up   -> fp16
__device__ __align__(128) __half g_wdh[(size_t)K_DIM   * H_DIM];   // w_down -> fp16
__device__ __align__(128) __half g_hid[(size_t)M_TOTAL * H_DIM];   // silu(g)*u in fp16

// ============================ helpers (plain sm_80+ PTX only) ============================
__device__ __forceinline__ uint32_t smem_u32(const void* p) {
    uint32_t a;
    asm("{ .reg .u64 t; cvta.to.shared.u64 t, %1; cvt.u32.u64 %0, t; }" : "=r"(a) : "l"(p));
    return a;
}
#define CP_ASYNC16(saddr, gptr) \
    asm volatile("cp.async.cg.shared.global [%0], [%1], 16;" :: "r"(saddr), "l"(gptr))
#define CP_COMMIT() asm volatile("cp.async.commit_group;" ::: "memory")
#define CP_WAIT(n)  asm volatile("cp.async.wait_group %0;" :: "n"(n) : "memory")

#define LDMATRIX_X4(R0, R1, R2, R3, addr) \
    asm volatile("ldmatrix.sync.aligned.m8n8.x4.shared.b16 {%0,%1,%2,%3}, [%4];" \
        : "=r"(R0), "=r"(R1), "=r"(R2), "=r"(R3) : "r"(addr))

__device__ __forceinline__ void mma_f16(float* c, const uint32_t* a, const uint32_t* b) {
    asm volatile(
        "mma.sync.aligned.m16n8k16.row.col.f32.f16.f16.f32 "
        "{%0,%1,%2,%3}, {%4,%5,%6,%7}, {%8,%9}, {%0,%1,%2,%3};"
        : "+f"(c[0]), "+f"(c[1]), "+f"(c[2]), "+f"(c[3])
        : "r"(a[0]), "r"(a[1]), "r"(a[2]), "r"(a[3]), "r"(b[0]), "r"(b[1]));
}

// ============================ tiling ============================
// Smem row = 32 halves (64B data) at 80B stride; 80 = 5*16 -> ldmatrix's 8 rows per
// phase land on 8 distinct 16B bank groups (conflict-free LDSM).
static constexpr int ROW_STRIDE_B = 80;
static constexpr int BK = 32;                          // k-halves per stage
static constexpr int STAGES = 4;

// gate/up kernel: 128 A rows + 64 Wg rows + 64 Wu rows = 256 rows/stage
static constexpr int STAGE_BYTES_GU = 256 * ROW_STRIDE_B;            // 20480
static constexpr int SMEM_BYTES_GU  = STAGES * STAGE_BYTES_GU;       // 81920 -> 2 CTA/SM
// down kernel: 64 A rows + 128 B rows = 192 rows/stage
static constexpr int STAGE_BYTES_D  = 192 * ROW_STRIDE_B;            // 15360
static constexpr int SMEM_BYTES_D   = STAGES * STAGE_BYTES_D;        // 61440 -> 2 CTA/SM

// ============================ kernel 1: fused gate/up GEMM + SwiGLU ============================
// grid: (H/64, M/128). CTA: gate[128x64] + up[128x64] sharing the A tile; silu*mul in regs;
// fp16 hidden out. 8 warps as 2x4; per-warp 64x16 gate AND up.
__global__ void __launch_bounds__(256, 2) gemm_gateup(
    const __half* __restrict__ X, const __half* __restrict__ Wg,
    const __half* __restrict__ Wu, __half* __restrict__ Hid) {
    extern __shared__ char smem[];
    const uint32_t sb = smem_u32(smem);

    const int tid = threadIdx.x;
    const int warp = tid >> 5, lane = tid & 31;
    const int warpM = warp >> 2, warpN = warp & 3;
    const int m0 = blockIdx.y * 128, n0 = blockIdx.x * 64;

    const int r  = tid >> 2;          // 0..63
    const int ch = tid & 3;           // 16B chunk in row

    const int KT = K_DIM / BK;        // 64

    auto load_stage = [&](int s, int kk) {
        const size_t kb = (size_t)kk * BK + ch * 8;      // in halves
        const uint32_t sd = sb + (uint32_t)(s * STAGE_BYTES_GU + r * ROW_STRIDE_B + ch * 16);
        CP_ASYNC16(sd,                       X  + (size_t)(m0 + r)      * K_DIM + kb);
        CP_ASYNC16(sd +  64 * ROW_STRIDE_B,  X  + (size_t)(m0 + 64 + r) * K_DIM + kb);
        CP_ASYNC16(sd + 128 * ROW_STRIDE_B,  Wg + (size_t)(n0 + r)      * K_DIM + kb);
        CP_ASYNC16(sd + 192 * ROW_STRIDE_B,  Wu + (size_t)(n0 + r)      * K_DIM + kb);
        CP_COMMIT();
    };

    float accg[4][2][4], accu[4][2][4];
    #pragma unroll
    for (int mt = 0; mt < 4; mt++)
        #pragma unroll
        for (int nt = 0; nt < 2; nt++)
            #pragma unroll
            for (int j = 0; j < 4; j++) { accg[mt][nt][j] = 0.f; accu[mt][nt][j] = 0.f; }

    for (int s = 0; s < STAGES - 1; s++) load_stage(s, s);

    const uint32_t a_lo = (uint32_t)((lane & 15) * ROW_STRIDE_B + (lane >> 4) * 16);
    const uint32_t b_lo = (uint32_t)(((lane & 7) + ((lane >> 4) << 3)) * ROW_STRIDE_B
                                     + (((lane >> 3) & 1) << 4));

    for (int i = 0; i < KT; i++) {
        CP_WAIT(2);
        __syncthreads();               // single barrier per iter (1-sync multistage)
        const int nk = i + STAGES - 1;
        if (nk < KT) load_stage(nk & (STAGES - 1), nk);
        else         CP_COMMIT();

        const uint32_t st = sb + (uint32_t)((i & (STAGES - 1)) * STAGE_BYTES_GU);
        #pragma unroll
        for (int ks = 0; ks < 2; ks++) {
            const uint32_t kB = (uint32_t)(ks * 32);   // 16 halves = 32 bytes
            uint32_t a[4][4], bg[4], bu[4];
            #pragma unroll
            for (int mt = 0; mt < 4; mt++) {
                const uint32_t addr = st + (uint32_t)((warpM * 64 + mt * 16) * ROW_STRIDE_B)
                                        + a_lo + kB;
                LDMATRIX_X4(a[mt][0], a[mt][1], a[mt][2], a[mt][3], addr);
            }
            {
                const uint32_t addr = st + (uint32_t)((128 + warpN * 16) * ROW_STRIDE_B)
                                        + b_lo + kB;
                LDMATRIX_X4(bg[0], bg[1], bg[2], bg[3], addr);
                LDMATRIX_X4(bu[0], bu[1], bu[2], bu[3], addr + 64 * ROW_STRIDE_B);
            }
            #pragma unroll
            for (int mt = 0; mt < 4; mt++) {
                mma_f16(accg[mt][0], a[mt], bg + 0);
                mma_f16(accg[mt][1], a[mt], bg + 2);
                mma_f16(accu[mt][0], a[mt], bu + 0);
                mma_f16(accu[mt][1], a[mt], bu + 2);
            }
        }
    }

    // epilogue: hid = silu(g) * u, fp16 pair stores
    const int g4 = lane >> 2, t4 = lane & 3;
    #pragma unroll
    for (int mt = 0; mt < 4; mt++) {
        const int row = m0 + warpM * 64 + mt * 16 + g4;
        #pragma unroll
        for (int nt = 0; nt < 2; nt++) {
            const int col = n0 + warpN * 16 + nt * 8 + 2 * t4;
            #pragma unroll
            for (int h = 0; h < 2; h++) {
                const float gx = accg[mt][nt][2 * h],     ux = accu[mt][nt][2 * h];
                const float gy = accg[mt][nt][2 * h + 1], uy = accu[mt][nt][2 * h + 1];
                const float vx = gx * ux / (1.0f + __expf(-gx));
                const float vy = gy * uy / (1.0f + __expf(-gy));
                *reinterpret_cast<__half2*>(Hid + (size_t)(row + 8 * h) * H_DIM + col) =
                    __floats2half2_rn(vx, vy);
            }
        }
    }
}

// ============================ kernel 2: down GEMM (fp16 in, fp32 out) ============================
// grid: (2048/128, M/64) = (16, 128) -> 2048 CTAs (kills wave quantization).
// CTA tile 64x128; 8 warps as 2x4; per-warp 32x32.
__global__ void __launch_bounds__(256, 2) gemm_down(
    const __half* __restrict__ A, const __half* __restrict__ B, float* __restrict__ C) {
    extern __shared__ char smem[];
    const uint32_t sb = smem_u32(smem);

    const int tid = threadIdx.x;
    const int warp = tid >> 5, lane = tid & 31;
    const int warpM = warp >> 2, warpN = warp & 3;
    const int m0 = blockIdx.y * 64, n0 = blockIdx.x * 128;

    const int r  = tid >> 2;          // 0..63
    const int ch = tid & 3;

    const int KT = H_DIM / BK;        // 256

    auto load_stage = [&](int s, int kk) {
        const size_t kb = (size_t)kk * BK + ch * 8;
        const uint32_t sd = sb + (uint32_t)(s * STAGE_BYTES_D + r * ROW_STRIDE_B + ch * 16);
        CP_ASYNC16(sd,                       A + (size_t)(m0 + r)      * H_DIM + kb);
        CP_ASYNC16(sd +  64 * ROW_STRIDE_B,  B + (size_t)(n0 + r)      * H_DIM + kb);
        CP_ASYNC16(sd + 128 * ROW_STRIDE_B,  B + (size_t)(n0 + 64 + r) * H_DIM + kb);
        CP_COMMIT();
    };

    float acc[2][4][4];
    #pragma unroll
    for (int mt = 0; mt < 2; mt++)
        #pragma unroll
        for (int nt = 0; nt < 4; nt++)
            #pragma unroll
            for (int j = 0; j < 4; j++) acc[mt][nt][j] = 0.f;

    for (int s = 0; s < STAGES - 1; s++) load_stage(s, s);

    const uint32_t a_lo = (uint32_t)((lane & 15) * ROW_STRIDE_B + (lane >> 4) * 16);
    const uint32_t b_lo = (uint32_t)(((lane & 7) + ((lane >> 4) << 3)) * ROW_STRIDE_B
                                     + (((lane >> 3) & 1) << 4));

    for (int i = 0; i < KT; i++) {
        CP_WAIT(2);
        __syncthreads();               // single barrier per iter
        const int nk = i + STAGES - 1;
        if (nk < KT) load_stage(nk & (STAGES - 1), nk);
        else         CP_COMMIT();

        const uint32_t st = sb + (uint32_t)((i & (STAGES - 1)) * STAGE_BYTES_D);
        #pragma unroll
        for (int ks = 0; ks < 2; ks++) {
            const uint32_t kB = (uint32_t)(ks * 32);
            uint32_t a[2][4], b[8];
            #pragma unroll
            for (int mt = 0; mt < 2; mt++) {
                const uint32_t addr = st + (uint32_t)((warpM * 32 + mt * 16) * ROW_STRIDE_B)
                                        + a_lo + kB;
                LDMATRIX_X4(a[mt][0], a[mt][1], a[mt][2], a[mt][3], addr);
            }
            {
                const uint32_t addr = st + (uint32_t)((64 + warpN * 32) * ROW_STRIDE_B)
                                        + b_lo + kB;
                LDMATRIX_X4(b[0], b[1], b[2], b[3], addr);
                LDMATRIX_X4(b[4], b[5], b[6], b[7], addr + 16 * ROW_STRIDE_B);
            }
            #pragma unroll
            for (int mt = 0; mt < 2; mt++)
                #pragma unroll
                for (int nt = 0; nt < 4; nt++)
                    mma_f16(acc[mt][nt], a[mt], b + 2 * nt);
        }
    }

    const int g4 = lane >> 2, t4 = lane & 3;
    #pragma unroll
    for (int mt = 0; mt < 2; mt++) {
        const int row = m0 + warpM * 32 + mt * 16 + g4;
        #pragma unroll
        for (int nt = 0; nt < 4; nt++) {
            const int col = n0 + warpN * 32 + nt * 8 + 2 * t4;
            *reinterpret_cast<float2*>(C + (size_t)row * K_DIM + col) =
                make_float2(acc[mt][nt][0], acc[mt][nt][1]);
            *reinterpret_cast<float2*>(C + (size_t)(row + 8) * K_DIM + col) =
                make_float2(acc[mt][nt][2], acc[mt][nt][3]);
        }
    }
}

// ============================ fused conversion kernel (4 arrays, one launch) ============================
struct ConvArgs {
    const float4* src[4];
    uint2* dst[4];
};

__global__ void __launch_bounds__(256) f32_to_f16_multi(ConvArgs args, int n4) {
    const float4* __restrict__ src = args.src[blockIdx.y];
    uint2* __restrict__ dst = args.dst[blockIdx.y];
    int i = blockIdx.x * blockDim.x + threadIdx.x;
    const int stride = gridDim.x * blockDim.x;
    for (; i < n4; i += stride) {
        const float4 v = src[i];
        const __half2 h0 = __floats2half2_rn(v.x, v.y);
        const __half2 h1 = __floats2half2_rn(v.z, v.w);
        uint2 o;
        o.x = *reinterpret_cast<const uint32_t*>(&h0);
        o.y = *reinterpret_cast<const uint32_t*>(&h1);
        dst[i] = o;
    }
}

// ============================ host side ============================
extern "C" void kernel_launch(void* const* d_in, const int* in_sizes, int n_in,
                              void* d_out, int out_size) {
    const float* x  = (const float*)d_in[0];
    const float* wg = (const float*)d_in[1];
    const float* wu = (const float*)d_in[2];
    const float* wd = (const float*)d_in[3];
    float* out = (float*)d_out;

    void *p_xh, *p_wgh, *p_wuh, *p_wdh, *p_hid;
    cudaGetSymbolAddress(&p_xh,  g_xh);
    cudaGetSymbolAddress(&p_wgh, g_wgh);
    cudaGetSymbolAddress(&p_wuh, g_wuh);
    cudaGetSymbolAddress(&p_wdh, g_wdh);
    cudaGetSymbolAddress(&p_hid, g_hid);

    cudaFuncSetAttribute(gemm_gateup, cudaFuncAttributeMaxDynamicSharedMemorySize, SMEM_BYTES_GU);
    cudaFuncSetAttribute(gemm_down,   cudaFuncAttributeMaxDynamicSharedMemorySize, SMEM_BYTES_D);

    // 1) fp32 -> fp16 for all four operands in one launch
    ConvArgs ca;
    ca.src[0] = (const float4*)x;  ca.dst[0] = (uint2*)p_xh;
    ca.src[1] = (const float4*)wg; ca.dst[1] = (uint2*)p_wgh;
    ca.src[2] = (const float4*)wu; ca.dst[2] = (uint2*)p_wuh;
    ca.src[3] = (const float4*)wd; ca.dst[3] = (uint2*)p_wdh;
    const int n4 = (M_TOTAL * K_DIM) / 4;   // all four arrays are equal-sized
    f32_to_f16_multi<<<dim3(1024, 4), 256>>>(ca, n4);

    // 2) fused gate/up + SwiGLU -> fp16 hidden
    gemm_gateup<<<dim3(H_DIM / 64, M_TOTAL / 128), 256, SMEM_BYTES_GU>>>(
        (const __half*)p_xh, (const __half*)p_wgh, (const __half*)p_wuh, (__half*)p_hid);

    // 3) down GEMM -> fp32 out
    gemm_down<<<dim3(K_DIM / 128, M_TOTAL / 64), 256, SMEM_BYTES_D>>>(
        (const __half*)p_hid, (const __half*)p_wdh, out);
}